// round 2
// baseline (speedup 1.0000x reference)
#include <cuda_runtime.h>
#include <cuda_bf16.h>
#include <math.h>
#include <stdint.h>

// Problem dims
#define T_  512
#define B_  64
#define E_  300
#define H_  512
#define L_  5
#define G3H 1536
#define M_  (T_*B_)          // 32768

// ---------------------------------------------------------------------------
// Scratch (device globals — no runtime allocation allowed)
// ---------------------------------------------------------------------------
__device__ float g_xp0[(size_t)M_ * G3H];   // layer-0 input projections [T*B, 3H]
__device__ float g_xp1[(size_t)M_ * G3H];   // layer-1 input projections
__device__ float g_h1 [(size_t)M_ * H_];    // layer-0 hidden outputs [T*B, H]
__device__ float g_h2 [(size_t)M_ * H_];    // layer-1 hidden outputs
__device__ unsigned g_ctr[512];             // barrier counters (2 layers x 8 groups, padded)

// ---------------------------------------------------------------------------
// f32x2 packed-FMA helpers (sm_100+)
// ---------------------------------------------------------------------------
__device__ __forceinline__ unsigned long long pk2(float lo, float hi) {
    unsigned long long r;
    asm("mov.b64 %0, {%1, %2};" : "=l"(r) : "f"(lo), "f"(hi));
    return r;
}
__device__ __forceinline__ void fma2(unsigned long long& acc,
                                     unsigned long long a, unsigned long long b) {
    asm("fma.rn.f32x2 %0, %1, %2, %0;" : "+l"(acc) : "l"(a), "l"(b));
}
__device__ __forceinline__ float2 unpk(unsigned long long v) {
    float x, y;
    asm("mov.b64 {%0, %1}, %2;" : "=f"(x), "=f"(y) : "l"(v));
    return make_float2(x, y);
}
__device__ __forceinline__ unsigned ld_acquire(const unsigned* p) {
    unsigned v;
    asm volatile("ld.acquire.gpu.u32 %0, [%1];" : "=r"(v) : "l"(p) : "memory");
    return v;
}
__device__ __forceinline__ float sigmoidf_(float x) {
    return 1.0f / (1.0f + __expf(-x));
}

union F4U { float4 f; unsigned long long u[2]; };
union F2U { float2 f; unsigned long long u; };

// ---------------------------------------------------------------------------
// init: zero barrier counters
// ---------------------------------------------------------------------------
__global__ void init_ctr_kernel() {
    g_ctr[threadIdx.x] = 0u;
}

// ---------------------------------------------------------------------------
// Projection GEMM: C[M,1536] = A[M,K] @ W[1536,K]^T + bias
//   GATHER: A row m = emb[texts[m]] (K=300) -> g_xp0
//   else:   A row m = g_h1[m]       (K=512) -> g_xp1
// 128(M) x 64(N) tile, BK=16, 256 threads, 8x4 per-thread via f32x2 (m-paired)
// ---------------------------------------------------------------------------
template <bool GATHER, int K>
__global__ __launch_bounds__(256) void proj_kernel(
    const float* __restrict__ Aparam, const int* __restrict__ gidx,
    const float* __restrict__ W, const float* __restrict__ bias)
{
    __shared__ float As[16][128];
    __shared__ float Bs[16][64];

    const float* Abase = GATHER ? Aparam : g_h1;
    float* C = GATHER ? g_xp0 : g_xp1;

    const int tid = threadIdx.x;
    const int tx = tid & 15;          // n group (4 cols)
    const int ty = tid >> 4;          // m group (8 rows)
    const int m0 = blockIdx.y * 128;
    const int n0 = blockIdx.x * 64;

    unsigned long long acc[4][4];
#pragma unroll
    for (int i = 0; i < 4; ++i)
#pragma unroll
        for (int j = 0; j < 4; ++j) acc[i][j] = 0ull;

    const int KT = (K + 15) >> 4;
    for (int kt = 0; kt < KT; ++kt) {
        const int k0 = kt << 4;
        // ---- A tile -> As[k][m] ----
#pragma unroll
        for (int p = 0; p < 2; ++p) {
            int v  = tid + p * 256;
            int m  = v & 127;
            int kv = v >> 7;                      // 0..3
            int k  = k0 + kv * 4;
            float4 av = make_float4(0.f, 0.f, 0.f, 0.f);
            if (k < K) {
                const float* arow;
                if (GATHER) arow = Abase + (size_t)__ldg(gidx + m0 + m) * K;
                else        arow = Abase + (size_t)(m0 + m) * K;
                av = *(const float4*)(arow + k);
            }
            As[kv*4+0][m] = av.x; As[kv*4+1][m] = av.y;
            As[kv*4+2][m] = av.z; As[kv*4+3][m] = av.w;
        }
        // ---- B tile -> Bs[k][n] ----
        {
            int n  = tid & 63;
            int kv = tid >> 6;                    // 0..3
            int k  = k0 + kv * 4;
            float4 bv = make_float4(0.f, 0.f, 0.f, 0.f);
            if (k < K) bv = *(const float4*)(W + (size_t)(n0 + n) * K + k);
            Bs[kv*4+0][n] = bv.x; Bs[kv*4+1][n] = bv.y;
            Bs[kv*4+2][n] = bv.z; Bs[kv*4+3][n] = bv.w;
        }
        __syncthreads();
        // ---- compute ----
#pragma unroll
        for (int k = 0; k < 16; ++k) {
            const float* ar = &As[k][ty * 8];
            unsigned long long a0 = *(const unsigned long long*)(ar + 0);
            unsigned long long a1 = *(const unsigned long long*)(ar + 2);
            unsigned long long a2 = *(const unsigned long long*)(ar + 4);
            unsigned long long a3 = *(const unsigned long long*)(ar + 6);
            float4 bv = *(const float4*)&Bs[k][tx * 4];
            unsigned long long b0 = pk2(bv.x, bv.x);
            unsigned long long b1 = pk2(bv.y, bv.y);
            unsigned long long b2 = pk2(bv.z, bv.z);
            unsigned long long b3 = pk2(bv.w, bv.w);
            fma2(acc[0][0], a0, b0); fma2(acc[0][1], a0, b1);
            fma2(acc[0][2], a0, b2); fma2(acc[0][3], a0, b3);
            fma2(acc[1][0], a1, b0); fma2(acc[1][1], a1, b1);
            fma2(acc[1][2], a1, b2); fma2(acc[1][3], a1, b3);
            fma2(acc[2][0], a2, b0); fma2(acc[2][1], a2, b1);
            fma2(acc[2][2], a2, b2); fma2(acc[2][3], a2, b3);
            fma2(acc[3][0], a3, b0); fma2(acc[3][1], a3, b1);
            fma2(acc[3][2], a3, b2); fma2(acc[3][3], a3, b3);
        }
        __syncthreads();
    }

    // ---- epilogue ----
    float4 bv = *(const float4*)(bias + n0 + tx * 4);
    float bb[4] = {bv.x, bv.y, bv.z, bv.w};
#pragma unroll
    for (int j = 0; j < 4; ++j) {
        float lo[4], hi[4];
#pragma unroll
        for (int n = 0; n < 4; ++n) {
            float2 u = unpk(acc[j][n]);
            lo[n] = u.x + bb[n];
            hi[n] = u.y + bb[n];
        }
        int m = m0 + ty * 8 + 2 * j;
        *(float4*)(C + (size_t)m       * G3H + n0 + tx * 4) = make_float4(lo[0], lo[1], lo[2], lo[3]);
        *(float4*)(C + (size_t)(m + 1) * G3H + n0 + tx * 4) = make_float4(hi[0], hi[1], hi[2], hi[3]);
    }
}

// ---------------------------------------------------------------------------
// Persistent GRU recurrence.
// 128 CTAs = 8 groups x 16 CTAs; group g owns batch rows [8g, 8g+8).
// CTA (gidx) owns hidden slice [gidx*32, gidx*32+32): Whh rows
// {i, 512+i, 1024+i} SMEM-resident. 256 threads = 8 warps, warp = k-slice
// (64 k each). h_{t-1} exchanged via L2 (ys history buffer) + group barrier.
// ---------------------------------------------------------------------------
#define WS_STRIDE 514
#define WS_F  (96 * WS_STRIDE)                 // 49344 floats
#define HS_F  4096                             // hs[8][512]
#define RED_F 3072                             // red[4kq][3g][8b][32i]
#define SMEM_REC_FLOATS (WS_F + HS_F + RED_F + 96)
#define SMEM_REC_BYTES  (SMEM_REC_FLOATS * 4)  // 226432 B

__global__ __launch_bounds__(256, 1) void rec_kernel(
    const float* __restrict__ Whh, const float* __restrict__ bhh, int layer)
{
    extern __shared__ float sm[];
    float* ws  = sm;                       // [96][514]
    float* hs  = sm + WS_F;                // [8][512]
    float* red = sm + WS_F + HS_F;         // [4][3][8][32]
    float* sb  = sm + WS_F + HS_F + RED_F; // [96]

    const float* xp = layer ? g_xp1 : g_xp0;
    float*       ys = layer ? g_h2  : g_h1;

    const int tid   = threadIdx.x;
    const int wid   = tid >> 5;            // 0..7 = k-slice
    const int li    = tid & 31;
    const int bid   = blockIdx.x;
    const int group = bid >> 4;            // 0..7
    const int gidx  = bid & 15;            // 0..15
    const int rb    = group * 8;
    const int ibase = gidx * 32;
    unsigned* ctr   = g_ctr + layer * 256 + group * 32;

    // ---- preload weight slice + bias slice ----
    for (int idx = tid; idx < 96 * 128; idx += 256) {
        int r  = idx >> 7;                         // 0..95
        int kv = idx & 127;
        int gr = (r >> 5) * 512 + ibase + (r & 31);
        float4 v = __ldg((const float4*)(Whh + (size_t)gr * 512 + kv * 4));
        float* w = ws + r * WS_STRIDE + kv * 4;
        w[0] = v.x; w[1] = v.y; w[2] = v.z; w[3] = v.w;
    }
    if (tid < 96) {
        int gr = (tid >> 5) * 512 + ibase + (tid & 31);
        sb[tid] = __ldg(bhh + gr);
    }
    __syncthreads();

    const float* wr0 = ws + (0  + li) * WS_STRIDE + wid * 64;
    const float* wr1 = ws + (32 + li) * WS_STRIDE + wid * 64;
    const float* wr2 = ws + (64 + li) * WS_STRIDE + wid * 64;
    const float* hb  = hs + wid * 64;

    const int bo = tid >> 5;               // reuse as elementwise batch? no:
    // elementwise mapping: output o = tid -> b = tid>>5, i = tid&31
    const int eb = tid >> 5;
    const int ei = tid & 31;

    for (int t = 0; t < T_; ++t) {
        // ---- prefetch xp (DRAM latency hidden behind staging + matvec) ----
        const float* xrow = xp + ((size_t)t * B_ + rb + eb) * G3H + ibase + ei;
        float xr = __ldg(xrow);
        float xz = __ldg(xrow + 512);
        float xn = __ldg(xrow + 1024);

        // ---- stage h_{t-1} ----
        if (t == 0) {
            for (int idx = tid; idx < HS_F; idx += 256) hs[idx] = 0.f;
        } else {
            const float* hp = ys + (size_t)(t - 1) * B_ * H_ + (size_t)rb * H_;
#pragma unroll
            for (int q = 0; q < 4; ++q) {
                int idx = tid + q * 256;           // 0..1023
                int b = idx >> 7, kv = idx & 127;
                float4 v = __ldcg((const float4*)(hp + (size_t)b * H_ + kv * 4));
                *(float4*)(hs + b * 512 + kv * 4) = v;
            }
        }
        __syncthreads();

        // ---- matvec partials over this warp's 64 k ----
        unsigned long long acc[3][8];
#pragma unroll
        for (int g = 0; g < 3; ++g)
#pragma unroll
            for (int b = 0; b < 8; ++b) acc[g][b] = 0ull;

#pragma unroll 8
        for (int it = 0; it < 16; ++it) {
            int kk = it * 4;
            unsigned long long h01[8], h23[8];
#pragma unroll
            for (int b = 0; b < 8; ++b) {
                F4U hv;
                hv.f = *(const float4*)(hb + b * 512 + kk);
                h01[b] = hv.u[0];
                h23[b] = hv.u[1];
            }
            F2U wa, wb;
            // gate 0
            wa.f = *(const float2*)(wr0 + kk);
            wb.f = *(const float2*)(wr0 + kk + 2);
#pragma unroll
            for (int b = 0; b < 8; ++b) { fma2(acc[0][b], wa.u, h01[b]); fma2(acc[0][b], wb.u, h23[b]); }
            // gate 1
            wa.f = *(const float2*)(wr1 + kk);
            wb.f = *(const float2*)(wr1 + kk + 2);
#pragma unroll
            for (int b = 0; b < 8; ++b) { fma2(acc[1][b], wa.u, h01[b]); fma2(acc[1][b], wb.u, h23[b]); }
            // gate 2
            wa.f = *(const float2*)(wr2 + kk);
            wb.f = *(const float2*)(wr2 + kk + 2);
#pragma unroll
            for (int b = 0; b < 8; ++b) { fma2(acc[2][b], wa.u, h01[b]); fma2(acc[2][b], wb.u, h23[b]); }
        }

        float v[3][8];
#pragma unroll
        for (int g = 0; g < 3; ++g)
#pragma unroll
            for (int b = 0; b < 8; ++b) {
                float2 u = unpk(acc[g][b]);
                v[g][b] = u.x + u.y;
            }

        // ---- two-pass cross-warp reduction into red[kq<4] ----
        if (wid < 4) {
#pragma unroll
            for (int g = 0; g < 3; ++g)
#pragma unroll
                for (int b = 0; b < 8; ++b)
                    red[((wid * 3 + g) * 8 + b) * 32 + li] = v[g][b];
        }
        __syncthreads();
        if (wid >= 4) {
            int kq = wid - 4;
#pragma unroll
            for (int g = 0; g < 3; ++g)
#pragma unroll
                for (int b = 0; b < 8; ++b)
                    red[((kq * 3 + g) * 8 + b) * 32 + li] += v[g][b];
        }
        __syncthreads();

        // ---- elementwise: one output (eb, ei) per thread ----
        float ghr = 0.f, ghz = 0.f, ghn = 0.f;
#pragma unroll
        for (int kq = 0; kq < 4; ++kq) {
            ghr += red[((kq * 3 + 0) * 8 + eb) * 32 + ei];
            ghz += red[((kq * 3 + 1) * 8 + eb) * 32 + ei];
            ghn += red[((kq * 3 + 2) * 8 + eb) * 32 + ei];
        }
        ghr += sb[ei];
        ghz += sb[32 + ei];
        ghn += sb[64 + ei];

        float r = sigmoidf_(xr + ghr);
        float z = sigmoidf_(xz + ghz);
        float n = tanhf(xn + r * ghn);
        float hprev = hs[eb * 512 + ibase + ei];
        float hnew = n + z * (hprev - n);

        __stcg(ys + ((size_t)t * B_ + rb + eb) * H_ + ibase + ei, hnew);

        // ---- group barrier ----
        __threadfence();
        __syncthreads();
        if (tid == 0) {
            atomicAdd(ctr, 1u);
            unsigned target = 16u * (unsigned)(t + 1);
            while (ld_acquire(ctr) < target) { }
        }
        __syncthreads();
    }
}

// ---------------------------------------------------------------------------
// Pool over batch + FC: out[t][l] = mean_b(h2[t,b,:]) . fc_W[l] + fc_b[l]
// ---------------------------------------------------------------------------
__global__ __launch_bounds__(256) void pool_fc_kernel(
    const float* __restrict__ fcW, const float* __restrict__ fcb,
    float* __restrict__ out)
{
    __shared__ float rbuf[5][256];
    const int t = blockIdx.x;
    const int tid = threadIdx.x;

    float s0 = 0.f, s1 = 0.f;
    const float* base = g_h2 + (size_t)t * B_ * H_ + tid * 2;
#pragma unroll 8
    for (int b = 0; b < B_; ++b) {
        float2 vv = *(const float2*)(base + (size_t)b * H_);
        s0 += vv.x; s1 += vv.y;
    }
    s0 *= (1.0f / 64.0f);
    s1 *= (1.0f / 64.0f);

#pragma unroll
    for (int l = 0; l < L_; ++l)
        rbuf[l][tid] = s0 * __ldg(fcW + l * H_ + tid * 2)
                     + s1 * __ldg(fcW + l * H_ + tid * 2 + 1);
    __syncthreads();

    for (int s = 128; s > 0; s >>= 1) {
        if (tid < s) {
#pragma unroll
            for (int l = 0; l < L_; ++l) rbuf[l][tid] += rbuf[l][tid + s];
        }
        __syncthreads();
    }
    if (tid < L_) out[t * L_ + tid] = rbuf[tid][0] + __ldg(fcb + tid);
}

// ---------------------------------------------------------------------------
// launcher
// ---------------------------------------------------------------------------
extern "C" void kernel_launch(void* const* d_in, const int* in_sizes, int n_in,
                              void* d_out, int out_size) {
    (void)in_sizes; (void)n_in; (void)out_size;
    const int*   texts = (const int*)  d_in[0];
    const float* emb   = (const float*)d_in[1];
    const float* Wih0  = (const float*)d_in[2];
    const float* Whh0  = (const float*)d_in[3];
    const float* bih0  = (const float*)d_in[4];
    const float* bhh0  = (const float*)d_in[5];
    const float* Wih1  = (const float*)d_in[6];
    const float* Whh1  = (const float*)d_in[7];
    const float* bih1  = (const float*)d_in[8];
    const float* bhh1  = (const float*)d_in[9];
    const float* fcW   = (const float*)d_in[10];
    const float* fcb   = (const float*)d_in[11];
    float* out = (float*)d_out;

    cudaFuncSetAttribute(rec_kernel,
                         cudaFuncAttributeMaxDynamicSharedMemorySize,
                         SMEM_REC_BYTES);

    init_ctr_kernel<<<1, 512>>>();
    proj_kernel<true, 300><<<dim3(24, 256), 256>>>(emb, texts, Wih0, bih0);
    rec_kernel<<<128, 256, SMEM_REC_BYTES>>>(Whh0, bhh0, 0);
    proj_kernel<false, 512><<<dim3(24, 256), 256>>>(nullptr, nullptr, Wih1, bih1);
    rec_kernel<<<128, 256, SMEM_REC_BYTES>>>(Whh1, bhh1, 1);
    pool_fc_kernel<<<512, 256>>>(fcW, fcb, out);
}